// round 2
// baseline (speedup 1.0000x reference)
#include <cuda_runtime.h>
#include <cstdint>

// StructAttentionLayer: B=16384, A=50, D=256, fp32.
//   e[b,a]   = attrs[b,a,:]·a_attr + entity[b,:]·a_ent
//   e        = leaky_relu(e, 0.2); attn = softmax_a(e) * A
//   out[b,:] = sum_a attn[b,a] * attrs[b,a,:]
//
// R2: 512-thread CTA (8 row-groups x 64 col-groups), v[7] float4 in regs
// (28 regs vs 52 in R1) -> 2 CTAs x 16 warps resident (50% occ) so one
// CTA's epilogue overlaps the other's HBM burst. attrs read exactly once.

#define A_NUM 50
#define D_DIM 256
#define ALPHA 0.2f
#define NROWS 7    // ceil(50/8)

__global__ __launch_bounds__(512, 2)
void struct_attn_kernel(const float* __restrict__ attrs,
                        const float* __restrict__ ent,
                        const float* __restrict__ aa,
                        float* __restrict__ out)
{
    const int b    = blockIdx.x;
    const int t    = threadIdx.x;
    const int rg   = t >> 6;          // row group 0..7
    const int c    = t & 63;          // column group: cols 4c..4c+3
    const int warp = t >> 5;
    const int lane = t & 31;

    __shared__ float  ep[A_NUM + 2][2];   // per-row warp partials (+entity dot in row 50)
    __shared__ float  e_s[52];            // logits -> attention weights
    __shared__ float4 part[8][64];        // weighted-sum row-group partials

    const float4* __restrict__ Arow =
        reinterpret_cast<const float4*>(attrs + (size_t)b * (A_NUM * D_DIM));

    const float4 aw = reinterpret_cast<const float4*>(aa)[c];   // a_attr cols 4c..4c+3

    // --- load my tile (<=7 float4 rows), front-batched LDG.128 ---
    float4 v[NROWS];
#pragma unroll
    for (int i = 0; i < NROWS; i++) {
        const int a = rg + 8 * i;
        v[i] = (a < A_NUM) ? Arow[a * (D_DIM / 4) + c]
                           : make_float4(0.f, 0.f, 0.f, 0.f);
    }

    // --- logits: per-row partial dot, reduced across the 2 warps covering the row ---
#pragma unroll
    for (int i = 0; i < NROWS; i++) {
        const int a = rg + 8 * i;
        float s = v[i].x * aw.x + v[i].y * aw.y + v[i].z * aw.z + v[i].w * aw.w;
        s += __shfl_xor_sync(0xffffffffu, s, 16);
        s += __shfl_xor_sync(0xffffffffu, s, 8);
        s += __shfl_xor_sync(0xffffffffu, s, 4);
        s += __shfl_xor_sync(0xffffffffu, s, 2);
        s += __shfl_xor_sync(0xffffffffu, s, 1);
        if (lane == 0 && a < A_NUM) ep[a][warp & 1] = s;
    }

    // --- entity dot (row-group 0: warps 0 and 1 cover all 256 cols) ---
    if (rg == 0) {
        const float4 ew = reinterpret_cast<const float4*>(aa + D_DIM)[c];  // a_ent
        const float4 ev = reinterpret_cast<const float4*>(ent + (size_t)b * D_DIM)[c];
        float p = ev.x * ew.x + ev.y * ew.y + ev.z * ew.z + ev.w * ew.w;
        p += __shfl_xor_sync(0xffffffffu, p, 16);
        p += __shfl_xor_sync(0xffffffffu, p, 8);
        p += __shfl_xor_sync(0xffffffffu, p, 4);
        p += __shfl_xor_sync(0xffffffffu, p, 2);
        p += __shfl_xor_sync(0xffffffffu, p, 1);
        if (lane == 0) ep[A_NUM][warp] = p;
    }
    __syncthreads();

    // --- combine partials + leaky relu ---
    if (t < A_NUM) {
        const float ed = ep[A_NUM][0] + ep[A_NUM][1];
        float e = ep[t][0] + ep[t][1] + ed;
        e_s[t] = (e > 0.f) ? e : ALPHA * e;
    }
    __syncthreads();

    // --- softmax over 50 (warp 0), scaled by A_NUM ---
    if (warp == 0) {
        float x0 = e_s[lane];
        float x1 = (lane < A_NUM - 32) ? e_s[lane + 32] : -1e30f;
        float m = fmaxf(x0, x1);
        m = fmaxf(m, __shfl_xor_sync(0xffffffffu, m, 16));
        m = fmaxf(m, __shfl_xor_sync(0xffffffffu, m, 8));
        m = fmaxf(m, __shfl_xor_sync(0xffffffffu, m, 4));
        m = fmaxf(m, __shfl_xor_sync(0xffffffffu, m, 2));
        m = fmaxf(m, __shfl_xor_sync(0xffffffffu, m, 1));
        float q0 = __expf(x0 - m);
        float q1 = (lane < A_NUM - 32) ? __expf(x1 - m) : 0.f;
        float ssum = q0 + q1;
        ssum += __shfl_xor_sync(0xffffffffu, ssum, 16);
        ssum += __shfl_xor_sync(0xffffffffu, ssum, 8);
        ssum += __shfl_xor_sync(0xffffffffu, ssum, 4);
        ssum += __shfl_xor_sync(0xffffffffu, ssum, 2);
        ssum += __shfl_xor_sync(0xffffffffu, ssum, 1);
        const float inv = (float)A_NUM / ssum;
        e_s[lane] = q0 * inv;
        if (lane < A_NUM - 32) e_s[lane + 32] = q1 * inv;
    }
    __syncthreads();

    // --- weighted sum over my rows (register-resident tile) ---
    float4 acc = make_float4(0.f, 0.f, 0.f, 0.f);
#pragma unroll
    for (int i = 0; i < NROWS; i++) {
        const int a = rg + 8 * i;
        const float w = (a < A_NUM) ? e_s[a] : 0.f;
        acc.x += w * v[i].x;
        acc.y += w * v[i].y;
        acc.z += w * v[i].z;
        acc.w += w * v[i].w;
    }
    part[rg][c] = acc;
    __syncthreads();

    // --- combine 8 row-groups and store (threads 0..63, coalesced STG.128) ---
    if (t < 64) {
        float4 r = part[0][t];
#pragma unroll
        for (int g = 1; g < 8; g++) {
            const float4 p = part[g][t];
            r.x += p.x; r.y += p.y; r.z += p.z; r.w += p.w;
        }
        reinterpret_cast<float4*>(out + (size_t)b * D_DIM)[t] = r;
    }
}

extern "C" void kernel_launch(void* const* d_in, const int* in_sizes, int n_in,
                              void* d_out, int out_size)
{
    const float* attrs = (const float*)d_in[0];   // [16384, 50, 256]
    const float* ent   = (const float*)d_in[1];   // [16384, 256]
    const float* aa    = (const float*)d_in[2];   // [512, 1]
    float* out         = (float*)d_out;           // [16384, 256]

    const int B = in_sizes[1] / D_DIM;            // 16384
    struct_attn_kernel<<<B, 512>>>(attrs, ent, aa, out);
}

// round 3
// speedup vs baseline: 1.7533x; 1.7533x over previous
#include <cuda_runtime.h>
#include <cstdint>

// StructAttentionLayer: B=16384, A=50, D=256, fp32.  HBM-bound (873MB once).
// R3: TMA bulk copy (cp.async.bulk) stages the 50x256 tile + entity row into
// SMEM; 256-thread CTA, ~40 regs, 4 CTAs/SM. Warp-per-row logits (no cross-
// warp combine), thread-per-column weighted sum (no partial combine).

#define A_NUM 50
#define D_DIM 256
#define ALPHA 0.2f
#define TILE_BYTES (A_NUM * D_DIM * 4)     // 51200
#define ENT_BYTES  (D_DIM * 4)             // 1024
#define TX_BYTES   (TILE_BYTES + ENT_BYTES)
#define DYN_SMEM   TX_BYTES

__global__ __launch_bounds__(256, 4)
void struct_attn_kernel(const float* __restrict__ attrs,
                        const float* __restrict__ ent,
                        const float* __restrict__ aa,
                        float* __restrict__ out)
{
    extern __shared__ __align__(128) float sm[];
    float* tile = sm;                        // tile[a*256 + d]
    float* ents = sm + A_NUM * D_DIM;        // ents[256]

    __shared__ float e_s[A_NUM + 2];         // logits -> weights; [A_NUM] = entity dot
    __shared__ __align__(8) unsigned long long mbar;

    const int b    = blockIdx.x;
    const int t    = threadIdx.x;
    const int warp = t >> 5;
    const int lane = t & 31;

    const uint32_t mbar_a = (uint32_t)__cvta_generic_to_shared(&mbar);
    const uint32_t tile_a = (uint32_t)__cvta_generic_to_shared(tile);
    const uint32_t ents_a = (uint32_t)__cvta_generic_to_shared(ents);

    if (t == 0) {
        asm volatile("mbarrier.init.shared.b64 [%0], 1;" :: "r"(mbar_a) : "memory");
    }
    __syncthreads();

    if (t == 0) {
        asm volatile("mbarrier.arrive.expect_tx.shared.b64 _, [%0], %1;"
                     :: "r"(mbar_a), "r"((uint32_t)TX_BYTES) : "memory");
        const float* gsrc = attrs + (size_t)b * (A_NUM * D_DIM);
        asm volatile("cp.async.bulk.shared::cta.global.mbarrier::complete_tx::bytes "
                     "[%0], [%1], %2, [%3];"
                     :: "r"(tile_a), "l"(gsrc), "r"((uint32_t)TILE_BYTES), "r"(mbar_a)
                     : "memory");
        const float* esrc = ent + (size_t)b * D_DIM;
        asm volatile("cp.async.bulk.shared::cta.global.mbarrier::complete_tx::bytes "
                     "[%0], [%1], %2, [%3];"
                     :: "r"(ents_a), "l"(esrc), "r"((uint32_t)ENT_BYTES), "r"(mbar_a)
                     : "memory");
    }

    // Overlap TMA latency: preload weight vector halves (2KB, L2-resident).
    const float4* aa4 = reinterpret_cast<const float4*>(aa);
    const float4 aw0 = aa4[lane];            // a_attr[lane*4 ..]
    const float4 aw1 = aa4[32 + lane];       // a_attr[128 + lane*4 ..]

    // Wait for TMA (phase 0), acquire so LDS below sees the data.
    asm volatile(
        "{\n\t"
        ".reg .pred P;\n\t"
        "WL%=:\n\t"
        "mbarrier.try_wait.parity.acquire.cta.shared::cta.b64 P, [%0], 0, 0x989680;\n\t"
        "@P bra WD%=;\n\t"
        "bra WL%=;\n\t"
        "WD%=:\n\t"
        "}" :: "r"(mbar_a) : "memory");

    // --- logits: warp w owns rows {w, w+8, ...}; row fully inside one warp ---
    const float4* tile4 = reinterpret_cast<const float4*>(tile);
#pragma unroll
    for (int k = 0; k < 7; k++) {
        const int a = warp + 8 * k;
        if (a < A_NUM) {
            const float4 v0 = tile4[a * 64 + lane];
            const float4 v1 = tile4[a * 64 + 32 + lane];
            float s = v0.x * aw0.x + v0.y * aw0.y + v0.z * aw0.z + v0.w * aw0.w
                    + v1.x * aw1.x + v1.y * aw1.y + v1.z * aw1.z + v1.w * aw1.w;
            s += __shfl_xor_sync(0xffffffffu, s, 16);
            s += __shfl_xor_sync(0xffffffffu, s, 8);
            s += __shfl_xor_sync(0xffffffffu, s, 4);
            s += __shfl_xor_sync(0xffffffffu, s, 2);
            s += __shfl_xor_sync(0xffffffffu, s, 1);
            if (lane == 0) e_s[a] = s;
        }
    }

    // --- entity dot (warp 7 has only 6 rows) ---
    if (warp == 7) {
        const float4* e4 = reinterpret_cast<const float4*>(ents);
        const float4 ev0 = e4[lane];
        const float4 ev1 = e4[32 + lane];
        const float4 ew0 = aa4[64 + lane];   // a_ent
        const float4 ew1 = aa4[96 + lane];
        float p = ev0.x * ew0.x + ev0.y * ew0.y + ev0.z * ew0.z + ev0.w * ew0.w
                + ev1.x * ew1.x + ev1.y * ew1.y + ev1.z * ew1.z + ev1.w * ew1.w;
        p += __shfl_xor_sync(0xffffffffu, p, 16);
        p += __shfl_xor_sync(0xffffffffu, p, 8);
        p += __shfl_xor_sync(0xffffffffu, p, 4);
        p += __shfl_xor_sync(0xffffffffu, p, 2);
        p += __shfl_xor_sync(0xffffffffu, p, 1);
        if (lane == 0) e_s[A_NUM] = p;
    }
    __syncthreads();

    // --- leaky-relu + softmax over 50 (warp 0), scaled by A_NUM ---
    if (warp == 0) {
        const float ed = e_s[A_NUM];
        float x0 = e_s[lane] + ed;
        x0 = (x0 > 0.f) ? x0 : ALPHA * x0;
        float x1 = -1e30f;
        if (lane < A_NUM - 32) {
            x1 = e_s[lane + 32] + ed;
            x1 = (x1 > 0.f) ? x1 : ALPHA * x1;
        }
        float m = fmaxf(x0, x1);
        m = fmaxf(m, __shfl_xor_sync(0xffffffffu, m, 16));
        m = fmaxf(m, __shfl_xor_sync(0xffffffffu, m, 8));
        m = fmaxf(m, __shfl_xor_sync(0xffffffffu, m, 4));
        m = fmaxf(m, __shfl_xor_sync(0xffffffffu, m, 2));
        m = fmaxf(m, __shfl_xor_sync(0xffffffffu, m, 1));
        const float q0 = __expf(x0 - m);
        const float q1 = (lane < A_NUM - 32) ? __expf(x1 - m) : 0.f;
        float ssum = q0 + q1;
        ssum += __shfl_xor_sync(0xffffffffu, ssum, 16);
        ssum += __shfl_xor_sync(0xffffffffu, ssum, 8);
        ssum += __shfl_xor_sync(0xffffffffu, ssum, 4);
        ssum += __shfl_xor_sync(0xffffffffu, ssum, 2);
        ssum += __shfl_xor_sync(0xffffffffu, ssum, 1);
        const float inv = (float)A_NUM / ssum;
        e_s[lane] = q0 * inv;
        if (lane < A_NUM - 32) e_s[lane + 32] = q1 * inv;
    }
    __syncthreads();

    // --- weighted sum: thread t owns output column t (conflict-free LDS.32) ---
    float a0 = 0.f, a1 = 0.f;
#pragma unroll
    for (int a = 0; a < A_NUM; a += 2) {
        a0 = fmaf(e_s[a],     tile[a * D_DIM + t],       a0);
        a1 = fmaf(e_s[a + 1], tile[(a + 1) * D_DIM + t], a1);
    }
    out[(size_t)b * D_DIM + t] = a0 + a1;
}

extern "C" void kernel_launch(void* const* d_in, const int* in_sizes, int n_in,
                              void* d_out, int out_size)
{
    const float* attrs = (const float*)d_in[0];   // [16384, 50, 256]
    const float* ent   = (const float*)d_in[1];   // [16384, 256]
    const float* aa    = (const float*)d_in[2];   // [512, 1]
    float* out         = (float*)d_out;           // [16384, 256]

    static int attr_set = 0;
    if (!attr_set) {
        cudaFuncSetAttribute(struct_attn_kernel,
                             cudaFuncAttributeMaxDynamicSharedMemorySize, DYN_SMEM);
        attr_set = 1;
    }

    const int B = in_sizes[1] / D_DIM;            // 16384
    struct_attn_kernel<<<B, 256, DYN_SMEM>>>(attrs, ent, aa, out);
}